// round 5
// baseline (speedup 1.0000x reference)
#include <cuda_runtime.h>
#include <cstdint>

// Shapes (fixed by setup_inputs):
//   k_cache: (B=4, H=8, D=128, 128, 64) f32 -> (BH=32, D=128, SFULL=8192)
//   v_cache: (B=4, H=8, 128, 64, D=128) f32 -> (BH=32, SFULL=8192, D=128)
//   S = 6144 (derived from out_size)
// out = stack([transpose_k(:, :, :S), v(:, :S, :)]) -> (2, BH, S, D)

#define BH_    32
#define D_     128
#define SFULL_ 8192

#define NBLK   1184              // 148 SMs x 8 resident CTAs: single wave
#define NSLOT  (NBLK / 2)        // 592 persistent CTAs per role

// Persistent fused kernel.
//   Odd blocks: V role  — grid-stride copy of 16 KB chunks, next-chunk loads
//               issued immediately after current-chunk stores (continuous MLP).
//   Even blocks: K role — 128(d) x 32(s) transpose tiles; next tile's LDGs
//               issued right after STS, in flight during the LDS/STG phase.
__global__ __launch_bounds__(256, 8) void fused_kv_persistent(
    const float*  __restrict__ kin,
    const float4* __restrict__ vin,
    float*        __restrict__ outk,
    float4*       __restrict__ outv,
    int S, int tilesPerBh, int nTiles)
{
    const int t    = threadIdx.x;
    const int slot = blockIdx.x >> 1;

    if (blockIdx.x & 1) {
        // ------------------------- V role -----------------------------------
        int id = slot;
        if (id >= nTiles) return;

        float4 v0, v1, v2, v3;
        {
            const int bh = id / tilesPerBh, jj = id - bh * tilesPerBh;
            const float4* src = vin + (size_t)bh * (SFULL_ * (D_ / 4))
                                    + (size_t)jj * 1024;
            v0 = src[t]; v1 = src[t + 256]; v2 = src[t + 512]; v3 = src[t + 768];
        }
        for (;;) {
            const int bh = id / tilesPerBh, jj = id - bh * tilesPerBh;
            float4* dst = outv + (size_t)bh * ((size_t)S * (D_ / 4))
                               + (size_t)jj * 1024;
            dst[t]       = v0;
            dst[t + 256] = v1;
            dst[t + 512] = v2;
            dst[t + 768] = v3;

            const int nid = id + NSLOT;
            if (nid >= nTiles) break;
            // Prefetch next chunk: LDGs in flight while loop wraps around.
            const int nbh = nid / tilesPerBh, njj = nid - nbh * tilesPerBh;
            const float4* nsrc = vin + (size_t)nbh * (SFULL_ * (D_ / 4))
                                     + (size_t)njj * 1024;
            v0 = nsrc[t]; v1 = nsrc[t + 256]; v2 = nsrc[t + 512]; v3 = nsrc[t + 768];
            id = nid;
        }
    } else {
        // ------------------------- K role -----------------------------------
        // tile[s][d], row stride 129:
        //   STS bank = (4f+k+d) mod 32 -> all 32 banks once per warp
        //   LDS bank = (s+d)    mod 32 -> conflict-free
        __shared__ float tile[32][129];

        int id = slot;
        if (id >= nTiles) return;

        float4 r0, r1, r2, r3;
        {
            const int bh = id / tilesPerBh, jj = id - bh * tilesPerBh;
            const float* src = kin + (size_t)bh * D_ * SFULL_ + jj * 32;
            r0 = *(const float4*)(src + (size_t)((t + 0)   >> 3) * SFULL_ + 4 * ((t + 0)   & 7));
            r1 = *(const float4*)(src + (size_t)((t + 256) >> 3) * SFULL_ + 4 * ((t + 256) & 7));
            r2 = *(const float4*)(src + (size_t)((t + 512) >> 3) * SFULL_ + 4 * ((t + 512) & 7));
            r3 = *(const float4*)(src + (size_t)((t + 768) >> 3) * SFULL_ + 4 * ((t + 768) & 7));
        }
        for (;;) {
            // Scatter current regs into the tile.
            {
                const int d0 = (t + 0) >> 3,   f0 = (t + 0) & 7;
                tile[4*f0+0][d0] = r0.x; tile[4*f0+1][d0] = r0.y;
                tile[4*f0+2][d0] = r0.z; tile[4*f0+3][d0] = r0.w;
                const int d1 = (t + 256) >> 3, f1 = (t + 256) & 7;
                tile[4*f1+0][d1] = r1.x; tile[4*f1+1][d1] = r1.y;
                tile[4*f1+2][d1] = r1.z; tile[4*f1+3][d1] = r1.w;
                const int d2 = (t + 512) >> 3, f2 = (t + 512) & 7;
                tile[4*f2+0][d2] = r2.x; tile[4*f2+1][d2] = r2.y;
                tile[4*f2+2][d2] = r2.z; tile[4*f2+3][d2] = r2.w;
                const int d3 = (t + 768) >> 3, f3 = (t + 768) & 7;
                tile[4*f3+0][d3] = r3.x; tile[4*f3+1][d3] = r3.y;
                tile[4*f3+2][d3] = r3.z; tile[4*f3+3][d3] = r3.w;
            }
            __syncthreads();   // tile ready

            // Prefetch next tile's loads (WAR on r*: STS consumed them at
            // issue). These stay in flight during the LDS/STG phase below.
            const int nid  = id + NSLOT;
            const bool more = (nid < nTiles);
            if (more) {
                const int nbh = nid / tilesPerBh, njj = nid - nbh * tilesPerBh;
                const float* nsrc = kin + (size_t)nbh * D_ * SFULL_ + njj * 32;
                r0 = *(const float4*)(nsrc + (size_t)((t + 0)   >> 3) * SFULL_ + 4 * ((t + 0)   & 7));
                r1 = *(const float4*)(nsrc + (size_t)((t + 256) >> 3) * SFULL_ + 4 * ((t + 256) & 7));
                r2 = *(const float4*)(nsrc + (size_t)((t + 512) >> 3) * SFULL_ + 4 * ((t + 512) & 7));
                r3 = *(const float4*)(nsrc + (size_t)((t + 768) >> 3) * SFULL_ + 4 * ((t + 768) & 7));
            }

            // Drain tile: each warp writes contiguous 128 B; block writes a
            // fully contiguous 16 KB output region.
            {
                const int bh = id / tilesPerBh, jj = id - bh * tilesPerBh;
                float* dst = outk + (size_t)bh * (size_t)S * D_
                                  + (size_t)(jj * 32) * D_;
#pragma unroll
                for (int i = 0; i < 16; ++i) {
                    const int e = t + i * 256;
                    dst[e] = tile[e >> 7][e & 127];
                }
            }

            if (!more) break;
            id = nid;
            __syncthreads();   // all LDS done before next STS overwrites tile
        }
    }
}

extern "C" void kernel_launch(void* const* d_in, const int* in_sizes, int n_in,
                              void* d_out, int out_size) {
    const float* k_cache = (const float*)d_in[0];
    const float* v_cache = (const float*)d_in[1];
    // seq_len fully determined by out_size: out = 2 * BH * S * D elems.
    const int S          = out_size / (2 * BH_ * D_);   // 6144
    const int tilesPerBh = S / 32;                      // 192
    const int nTiles     = BH_ * tilesPerBh;            // 6144 per role

    float*  out_k = (float*)d_out;                                  // (BH,S,D)
    float4* out_v = (float4*)((float*)d_out + (size_t)BH_ * S * D_);

    dim3 block(256, 1, 1);
    dim3 grid(NBLK, 1, 1);                                          // 1184
    fused_kv_persistent<<<grid, block>>>(k_cache, (const float4*)v_cache,
                                         out_k, out_v, S, tilesPerBh, nTiles);
}

// round 6
// speedup vs baseline: 1.1256x; 1.1256x over previous
#include <cuda_runtime.h>
#include <cstdint>

// Shapes (fixed by setup_inputs):
//   k_cache: (B=4, H=8, D=128, 128, 64) f32 -> (BH=32, D=128, SFULL=8192)
//   v_cache: (B=4, H=8, 128, 64, D=128) f32 -> (BH=32, SFULL=8192, D=128)
//   S = 6144 (derived from out_size)
// out = stack([transpose_k(:, :, :S), v(:, :S, :)]) -> (2, BH, S, D)

#define BH_    32
#define D_     128
#define SFULL_ 8192

// sigma(s): bit-rotate of 5-bit s -> low 3 bits become (s>>2), ensuring
// XOR-swizzled cells are conflict-free for BOTH scalar STS and LDS.128.
__device__ __forceinline__ int sigma5(int s) {
    return ((s & 3) << 3) | (s >> 2);
}

// Fused kernel (R2 grid structure, proven best):
//   Even blocks: K-transpose tile (d=128 x s=32) via XOR-swizzled flat smem,
//                drained with LDS.128 + STG.128 (16 KB contiguous output).
//   Odd blocks:  V copy of 1024 float4 (16 KB), 4-deep batched MLP.
__global__ __launch_bounds__(256, 8) void fused_kv_kernel(
    const float*  __restrict__ kin,
    const float4* __restrict__ vin,
    float4*       __restrict__ outk,
    float4*       __restrict__ outv,
    int S, int tilesPerBh)
{
    const int b  = blockIdx.x;
    const int t  = threadIdx.x;
    const int id = b >> 1;
    const int bh = id / tilesPerBh;
    const int jj = id - bh * tilesPerBh;

    if (b & 1) {
        // ---------------- V copy: contiguous 16 KB chunk --------------------
        const float4* src = vin  + (size_t)bh * (SFULL_ * (D_ / 4)) + (size_t)jj * 1024;
        float4*       dst = outv + (size_t)bh * ((size_t)S * (D_ / 4)) + (size_t)jj * 1024;

        float4 v0 = src[t];
        float4 v1 = src[t + 256];
        float4 v2 = src[t + 512];
        float4 v3 = src[t + 768];
        dst[t]       = v0;
        dst[t + 256] = v1;
        dst[t + 512] = v2;
        dst[t + 768] = v3;
    } else {
        // -------------- K transpose: (D=128, s=32) -> (s=32, D=128) ---------
        // Flat 32(s) x 32(q) float4 tile, cell (s,q) stored at p = q ^ sigma(s).
        __shared__ float tile[32 * 128];   // 16 KB, no padding

        const int s0 = jj * 32;
        const float*  src = kin + (size_t)bh * D_ * SFULL_ + s0;
        float4*       dst = outk + ((size_t)bh * (size_t)S * D_
                                    + (size_t)s0 * D_) / 4;

        // Load: 1024 float4 (each = 4 consecutive s at fixed d), 4-deep MLP.
        float4 r[4];
#pragma unroll
        for (int i = 0; i < 4; ++i) {
            const int idx = t + i * 256;
            const int d = idx >> 3;       // 0..127
            const int f = idx & 7;        // float4 index along s
            r[i] = *(const float4*)(src + (size_t)d * SFULL_ + 4 * f);
        }

        // Scatter to swizzled smem. For float4 at (d, f): component k lands
        // at s = 4f+k, element (d&3) of cell (s, d>>2) at physical col
        // p = (d>>2) ^ sigma(s). Conflict-free: banks = 4*((q0^sigma)&7)+r
        // cover all 32 exactly once per STS.
#pragma unroll
        for (int i = 0; i < 4; ++i) {
            const int idx = t + i * 256;
            const int d = idx >> 3;
            const int f = idx & 7;
            const int q = d >> 2;
            const int rr = d & 3;
#pragma unroll
            for (int k = 0; k < 4; ++k) {
                const int s = 4 * f + k;
                const int p = q ^ sigma5(s);
                const float comp = (k == 0) ? r[i].x : (k == 1) ? r[i].y
                                 : (k == 2) ? r[i].z : r[i].w;
                tile[s * 128 + p * 4 + rr] = comp;
            }
        }
        __syncthreads();

        // Drain: 1024 float4; warp has s fixed, q=lane -> p distinct ->
        // LDS.128 conflict-free; STG.128 writes 512 B contiguous per warp,
        // block writes a fully contiguous 16 KB output region.
        const float4* tile4 = (const float4*)tile;
#pragma unroll
        for (int i = 0; i < 4; ++i) {
            const int e = t + i * 256;    // 0..1023
            const int s = e >> 5;         // 0..31
            const int q = e & 31;         // 0..31
            const int p = q ^ sigma5(s);
            dst[e] = tile4[s * 32 + p];
        }
    }
}

extern "C" void kernel_launch(void* const* d_in, const int* in_sizes, int n_in,
                              void* d_out, int out_size) {
    const float* k_cache = (const float*)d_in[0];
    const float* v_cache = (const float*)d_in[1];
    // seq_len fully determined by out_size: out = 2 * BH * S * D elems.
    const int S = out_size / (2 * BH_ * D_);        // 6144
    const int tilesPerBh = S / 32;                  // 192

    float4* out_k = (float4*)d_out;                                 // (BH,S,D)
    float4* out_v = (float4*)((float*)d_out + (size_t)BH_ * S * D_);

    dim3 block(256, 1, 1);
    dim3 grid((unsigned)(2 * BH_ * tilesPerBh), 1, 1);              // 12288
    fused_kv_kernel<<<grid, block>>>(k_cache, (const float4*)v_cache,
                                     out_k, out_v, S, tilesPerBh);
}